// round 2
// baseline (speedup 1.0000x reference)
#include <cuda_runtime.h>
#include <cuda_fp16.h>
#include <cstdint>

#define NROW 8192
#define FDIM 256
#define MT   64
#define KC   64

// Scratch (device globals; no runtime allocation)
__device__ float   g_h [NROW * FDIM];   // h = input @ W  (fp32)
__device__ __half  g_hh[NROW * FDIM];   // h in fp16 (B operand)
__device__ float4  g_dE[NROW];          // (dst, e^dst, e^{0.2 dst}, src)
__device__ float2  g_C [NROW];          // (e^src/Z, e^{0.2 src}/Z)

static __device__ __forceinline__ uint32_t smem_u32(const void* p) {
    return (uint32_t)__cvta_generic_to_shared(p);
}

// ---------------------------------------------------------------------------
// K1: h = input @ W   (fp32 FFMA, 32 rows per CTA, thread = output column)
// ---------------------------------------------------------------------------
__global__ void __launch_bounds__(256) k1_gemm_h(const float* __restrict__ x,
                                                 const float* __restrict__ W) {
    __shared__ float sx[32][256];
    const int tid  = threadIdx.x;
    const int row0 = blockIdx.x * 32;

#pragma unroll
    for (int it = 0; it < 8; ++it) {
        int idx = tid + it * 256;          // 0..2047 float4s
        int r   = idx >> 6;
        int c4  = (idx & 63) << 2;
        *(float4*)(&sx[r][c4]) =
            *(const float4*)(&x[(size_t)(row0 + r) * FDIM + c4]);
    }
    __syncthreads();

    float acc[32];
#pragma unroll
    for (int r = 0; r < 32; ++r) acc[r] = 0.f;

    const int f = tid;
    for (int k = 0; k < 256; k += 4) {
        float w0 = __ldg(&W[(k + 0) * FDIM + f]);
        float w1 = __ldg(&W[(k + 1) * FDIM + f]);
        float w2 = __ldg(&W[(k + 2) * FDIM + f]);
        float w3 = __ldg(&W[(k + 3) * FDIM + f]);
#pragma unroll
        for (int r = 0; r < 32; ++r) {
            float4 v = *(const float4*)(&sx[r][k]);
            acc[r] = fmaf(v.x, w0, acc[r]);
            acc[r] = fmaf(v.y, w1, acc[r]);
            acc[r] = fmaf(v.z, w2, acc[r]);
            acc[r] = fmaf(v.w, w3, acc[r]);
        }
    }
#pragma unroll
    for (int r = 0; r < 32; ++r)
        g_h[(size_t)(row0 + r) * FDIM + f] = acc[r];
}

// ---------------------------------------------------------------------------
// K2: per-row src/dst projections, exp tables, fp16 copy of h.
//     1 warp per row, 8 rows per CTA.
// ---------------------------------------------------------------------------
__global__ void __launch_bounds__(256) k2_vec(const float* __restrict__ a) {
    const int tid = threadIdx.x;
    const int wid = tid >> 5, lane = tid & 31;
    const int row = blockIdx.x * 8 + wid;
    const float* hr = g_h + (size_t)row * FDIM;

    float s1 = 0.f, s2 = 0.f;
#pragma unroll
    for (int i = 0; i < 8; ++i) {
        int c = lane + i * 32;
        float v = hr[c];
        g_hh[(size_t)row * FDIM + c] = __float2half(v);
        s1 += v * __ldg(&a[c]);          // src contribution
        s2 += v * __ldg(&a[FDIM + c]);   // dst contribution
    }
#pragma unroll
    for (int off = 16; off; off >>= 1) {
        s1 += __shfl_xor_sync(0xffffffffu, s1, off);
        s2 += __shfl_xor_sync(0xffffffffu, s2, off);
    }
    if (lane == 0)
        g_dE[row] = make_float4(s2, expf(s2), expf(0.2f * s2), s1);
}

// ---------------------------------------------------------------------------
// K3: per-row softmax normalizers. 16 rows per CTA, one adj pass.
//     S1 = sum over {adj & (src_i+dst_j>0)} of e^dst ; S2 else-branch with e^{0.2 dst}
// ---------------------------------------------------------------------------
__global__ void __launch_bounds__(256) k3_stats(const int* __restrict__ adj) {
    __shared__ float s_src[16];
    __shared__ float red1[16][8];
    __shared__ float red2[16][8];
    const int tid  = threadIdx.x;
    const int row0 = blockIdx.x * 16;
    if (tid < 16) s_src[tid] = g_dE[row0 + tid].w;
    __syncthreads();

    float S1[16], S2[16];
#pragma unroll
    for (int r = 0; r < 16; ++r) { S1[r] = 0.f; S2[r] = 0.f; }

    for (int s = 0; s < 8; ++s) {
        const int j0 = tid * 4 + s * 1024;
        float4 d[4];
#pragma unroll
        for (int u = 0; u < 4; ++u) d[u] = __ldg(&g_dE[j0 + u]);
#pragma unroll
        for (int r = 0; r < 16; ++r) {
            const int4 a4 =
                *(const int4*)(&adj[(size_t)(row0 + r) * NROW + j0]);
            const float src = s_src[r];
            const int av[4] = {a4.x, a4.y, a4.z, a4.w};
#pragma unroll
            for (int u = 0; u < 4; ++u) {
                const bool nb  = av[u] > 0;
                const bool pos = (src + d[u].x) > 0.f;
                S1[r] += (nb && pos)  ? d[u].y : 0.f;
                S2[r] += (nb && !pos) ? d[u].z : 0.f;
            }
        }
    }
#pragma unroll
    for (int r = 0; r < 16; ++r) {
#pragma unroll
        for (int off = 16; off; off >>= 1) {
            S1[r] += __shfl_xor_sync(0xffffffffu, S1[r], off);
            S2[r] += __shfl_xor_sync(0xffffffffu, S2[r], off);
        }
    }
    const int wid = tid >> 5, lane = tid & 31;
    if (lane == 0) {
#pragma unroll
        for (int r = 0; r < 16; ++r) { red1[r][wid] = S1[r]; red2[r][wid] = S2[r]; }
    }
    __syncthreads();
    if (tid < 16) {
        float t1 = 0.f, t2 = 0.f;
#pragma unroll
        for (int w = 0; w < 8; ++w) { t1 += red1[tid][w]; t2 += red2[tid][w]; }
        const float src = s_src[tid];
        const float e1 = expf(src), e2 = expf(0.2f * src);
        const float inv = 1.0f / (e1 * t1 + e2 * t2);
        g_C[row0 + tid] = make_float2(e1 * inv, e2 * inv);
    }
}

// ---------------------------------------------------------------------------
// K4: fused masked-softmax x GEMM.  Per CTA: 64 output rows x 256 cols.
//     Stream adj in 64x64 chunks, build P tile (fp16) in smem, HMMA against
//     fp16 h tiles, fp32 accumulate, ReLU epilogue.
// ---------------------------------------------------------------------------
__global__ void __launch_bounds__(256) k4_main(const int* __restrict__ adj,
                                               float* __restrict__ out) {
    __shared__ __half sP[MT][72];     // P tile, +8 halves pad (ldmatrix-safe)
    __shared__ __half sH[KC][264];    // h tile, +8 halves pad
    __shared__ float2 sC[MT];
    __shared__ float  sSrc[MT];       // src_i per output row  (round-1 bugfix)

    const int tid  = threadIdx.x;
    const int row0 = blockIdx.x * MT;
    const int wid  = tid >> 5, lane = tid & 31;
    const int wm = (wid & 3) * 16;    // warp m offset (4 warps over M)
    const int wn = (wid >> 2) * 128;  // warp n offset (2 warps over N)

    if (tid < MT) {
        sC[tid]   = g_C[row0 + tid];
        sSrc[tid] = g_dE[row0 + tid].w;   // src of ROW node i
    }

    float acc[16][4];
#pragma unroll
    for (int nt = 0; nt < 16; ++nt)
#pragma unroll
        for (int q = 0; q < 4; ++q) acc[nt][q] = 0.f;

    for (int j0 = 0; j0 < NROW; j0 += KC) {
        __syncthreads();  // previous chunk's MMAs done (also covers sC/sSrc init)

        // ---- generate P tile: 64x64, thread handles 4 int4 groups ----
#pragma unroll
        for (int it = 0; it < 4; ++it) {
            const int idx = tid + it * 256;
            const int m   = idx >> 4;
            const int jq  = (idx & 15) << 2;
            const int4 a4 =
                *(const int4*)(&adj[(size_t)(row0 + m) * NROW + j0 + jq]);
            const float2 cc = sC[m];
            const float src = sSrc[m];
            const int av[4] = {a4.x, a4.y, a4.z, a4.w};
            float pv[4];
#pragma unroll
            for (int u = 0; u < 4; ++u) {
                const float4 de = __ldg(&g_dE[j0 + jq + u]);
                const float t = src + de.x;                        // src_i + dst_j
                const float p = (t > 0.f) ? (cc.x * de.y) : (cc.y * de.z);
                pv[u] = (av[u] > 0) ? p : 0.f;
            }
            *(__half2*)(&sP[m][jq])     = __floats2half2_rn(pv[0], pv[1]);
            *(__half2*)(&sP[m][jq + 2]) = __floats2half2_rn(pv[2], pv[3]);
        }

        // ---- load h tile: 64 x 256 halves ----
#pragma unroll
        for (int it = 0; it < 8; ++it) {
            const int idx = tid + it * 256;
            const int r   = idx >> 5;
            const int c8  = (idx & 31) << 3;
            const uint4 v =
                *(const uint4*)(&g_hh[(size_t)(j0 + r) * FDIM + c8]);
            *(uint4*)(&sH[r][c8]) = v;
        }
        __syncthreads();

        // ---- MMA: 4 k-steps of 16 ----
#pragma unroll
        for (int kk = 0; kk < KC; kk += 16) {
            uint32_t Af[4];
            {
                const uint32_t addr = smem_u32(
                    &sP[wm + (lane & 15)][kk + ((lane >> 4) << 3)]);
                asm volatile(
                    "ldmatrix.sync.aligned.m8n8.x4.shared.b16 "
                    "{%0,%1,%2,%3}, [%4];\n"
                    : "=r"(Af[0]), "=r"(Af[1]), "=r"(Af[2]), "=r"(Af[3])
                    : "r"(addr));
            }
#pragma unroll
            for (int nt2 = 0; nt2 < 8; ++nt2) {
                uint32_t Bf[4];
                const uint32_t baddr = smem_u32(
                    &sH[kk + (lane & 15)][wn + nt2 * 16 + ((lane >> 4) << 3)]);
                asm volatile(
                    "ldmatrix.sync.aligned.m8n8.x4.trans.shared.b16 "
                    "{%0,%1,%2,%3}, [%4];\n"
                    : "=r"(Bf[0]), "=r"(Bf[1]), "=r"(Bf[2]), "=r"(Bf[3])
                    : "r"(baddr));
                asm volatile(
                    "mma.sync.aligned.m16n8k16.row.col.f32.f16.f16.f32 "
                    "{%0,%1,%2,%3}, {%4,%5,%6,%7}, {%8,%9}, {%0,%1,%2,%3};\n"
                    : "+f"(acc[2 * nt2][0]), "+f"(acc[2 * nt2][1]),
                      "+f"(acc[2 * nt2][2]), "+f"(acc[2 * nt2][3])
                    : "r"(Af[0]), "r"(Af[1]), "r"(Af[2]), "r"(Af[3]),
                      "r"(Bf[0]), "r"(Bf[1]));
                asm volatile(
                    "mma.sync.aligned.m16n8k16.row.col.f32.f16.f16.f32 "
                    "{%0,%1,%2,%3}, {%4,%5,%6,%7}, {%8,%9}, {%0,%1,%2,%3};\n"
                    : "+f"(acc[2 * nt2 + 1][0]), "+f"(acc[2 * nt2 + 1][1]),
                      "+f"(acc[2 * nt2 + 1][2]), "+f"(acc[2 * nt2 + 1][3])
                    : "r"(Af[0]), "r"(Af[1]), "r"(Af[2]), "r"(Af[3]),
                      "r"(Bf[2]), "r"(Bf[3]));
            }
        }
    }

    // ---- epilogue: ReLU, fp32 store ----
    const int g  = lane >> 2;
    const int tq = lane & 3;
#pragma unroll
    for (int nt = 0; nt < 16; ++nt) {
        const int n  = wn + nt * 8 + tq * 2;
        const int r0 = row0 + wm + g;
        float2 v0 = make_float2(fmaxf(acc[nt][0], 0.f), fmaxf(acc[nt][1], 0.f));
        float2 v1 = make_float2(fmaxf(acc[nt][2], 0.f), fmaxf(acc[nt][3], 0.f));
        *(float2*)(&out[(size_t)r0 * FDIM + n])       = v0;
        *(float2*)(&out[(size_t)(r0 + 8) * FDIM + n]) = v1;
    }
}

// ---------------------------------------------------------------------------
extern "C" void kernel_launch(void* const* d_in, const int* in_sizes, int n_in,
                              void* d_out, int out_size) {
    const float* input_ = (const float*)d_in[0];
    const int*   adj    = (const int*)d_in[1];
    const float* W      = (const float*)d_in[2];
    const float* a      = (const float*)d_in[3];
    float*       out    = (float*)d_out;

    k1_gemm_h<<<NROW / 32, 256>>>(input_, W);
    k2_vec<<<NROW / 8, 256>>>(a);
    k3_stats<<<NROW / 16, 256>>>(adj);
    k4_main<<<NROW / MT, 256>>>(adj, out);
}

// round 3
// speedup vs baseline: 1.1697x; 1.1697x over previous
#include <cuda_runtime.h>
#include <cuda_fp16.h>
#include <cstdint>

#define NROW 8192
#define FDIM 256
#define MT   32     // output rows per CTA (k4)
#define KC   64     // j-chunk

// Scratch (device globals; no runtime allocation)
__device__ float   g_h [NROW * FDIM];   // h = input @ W  (fp32)
__device__ __half  g_hh[NROW * FDIM];   // h in fp16 (B operand)
__device__ float4  g_dE[NROW];          // (dst, e^dst, e^{0.2 dst}, src)
__device__ float2  g_C [NROW];          // (e^src/Z, e^{0.2 src}/Z)

static __device__ __forceinline__ uint32_t smem_u32(const void* p) {
    return (uint32_t)__cvta_generic_to_shared(p);
}
static __device__ __forceinline__ void cp16(uint32_t dst, const void* src) {
    asm volatile("cp.async.cg.shared.global [%0], [%1], 16;\n"
                 :: "r"(dst), "l"(src));
}
static __device__ __forceinline__ void cp_commit() {
    asm volatile("cp.async.commit_group;\n" ::: "memory");
}
static __device__ __forceinline__ void cp_wait0() {
    asm volatile("cp.async.wait_group 0;\n" ::: "memory");
}

// ---------------------------------------------------------------------------
// K1: h = input @ W   (fp32 FFMA, 32 rows per CTA, thread = output column)
// ---------------------------------------------------------------------------
__global__ void __launch_bounds__(256) k1_gemm_h(const float* __restrict__ x,
                                                 const float* __restrict__ W) {
    __shared__ float sx[32][256];
    const int tid  = threadIdx.x;
    const int row0 = blockIdx.x * 32;

#pragma unroll
    for (int it = 0; it < 8; ++it) {
        int idx = tid + it * 256;
        int r   = idx >> 6;
        int c4  = (idx & 63) << 2;
        *(float4*)(&sx[r][c4]) =
            *(const float4*)(&x[(size_t)(row0 + r) * FDIM + c4]);
    }
    __syncthreads();

    float acc[32];
#pragma unroll
    for (int r = 0; r < 32; ++r) acc[r] = 0.f;

    const int f = tid;
    for (int k = 0; k < 256; k += 4) {
        float w0 = __ldg(&W[(k + 0) * FDIM + f]);
        float w1 = __ldg(&W[(k + 1) * FDIM + f]);
        float w2 = __ldg(&W[(k + 2) * FDIM + f]);
        float w3 = __ldg(&W[(k + 3) * FDIM + f]);
#pragma unroll
        for (int r = 0; r < 32; ++r) {
            float4 v = *(const float4*)(&sx[r][k]);
            acc[r] = fmaf(v.x, w0, acc[r]);
            acc[r] = fmaf(v.y, w1, acc[r]);
            acc[r] = fmaf(v.z, w2, acc[r]);
            acc[r] = fmaf(v.w, w3, acc[r]);
        }
    }
#pragma unroll
    for (int r = 0; r < 32; ++r)
        g_h[(size_t)(row0 + r) * FDIM + f] = acc[r];
}

// ---------------------------------------------------------------------------
// K2: per-row src/dst projections, exp tables, fp16 copy of h.
// ---------------------------------------------------------------------------
__global__ void __launch_bounds__(256) k2_vec(const float* __restrict__ a) {
    const int tid = threadIdx.x;
    const int wid = tid >> 5, lane = tid & 31;
    const int row = blockIdx.x * 8 + wid;
    const float* hr = g_h + (size_t)row * FDIM;

    float s1 = 0.f, s2 = 0.f;
#pragma unroll
    for (int i = 0; i < 8; ++i) {
        int c = lane + i * 32;
        float v = hr[c];
        g_hh[(size_t)row * FDIM + c] = __float2half(v);
        s1 += v * __ldg(&a[c]);          // src contribution
        s2 += v * __ldg(&a[FDIM + c]);   // dst contribution
    }
#pragma unroll
    for (int off = 16; off; off >>= 1) {
        s1 += __shfl_xor_sync(0xffffffffu, s1, off);
        s2 += __shfl_xor_sync(0xffffffffu, s2, off);
    }
    if (lane == 0)
        g_dE[row] = make_float4(s2, expf(s2), expf(0.2f * s2), s1);
}

// ---------------------------------------------------------------------------
// K3: per-row softmax normalizers (one adj pass).
// ---------------------------------------------------------------------------
__global__ void __launch_bounds__(256) k3_stats(const int* __restrict__ adj) {
    __shared__ float s_src[16];
    __shared__ float red1[16][8];
    __shared__ float red2[16][8];
    const int tid  = threadIdx.x;
    const int row0 = blockIdx.x * 16;
    if (tid < 16) s_src[tid] = g_dE[row0 + tid].w;
    __syncthreads();

    float S1[16], S2[16];
#pragma unroll
    for (int r = 0; r < 16; ++r) { S1[r] = 0.f; S2[r] = 0.f; }

    for (int s = 0; s < 8; ++s) {
        const int j0 = tid * 4 + s * 1024;
        float4 d[4];
#pragma unroll
        for (int u = 0; u < 4; ++u) d[u] = __ldg(&g_dE[j0 + u]);
#pragma unroll
        for (int r = 0; r < 16; ++r) {
            const int4 a4 =
                *(const int4*)(&adj[(size_t)(row0 + r) * NROW + j0]);
            const float src = s_src[r];
            const int av[4] = {a4.x, a4.y, a4.z, a4.w};
#pragma unroll
            for (int u = 0; u < 4; ++u) {
                const bool nb  = av[u] > 0;
                const bool pos = (src + d[u].x) > 0.f;
                S1[r] += (nb && pos)  ? d[u].y : 0.f;
                S2[r] += (nb && !pos) ? d[u].z : 0.f;
            }
        }
    }
#pragma unroll
    for (int r = 0; r < 16; ++r) {
#pragma unroll
        for (int off = 16; off; off >>= 1) {
            S1[r] += __shfl_xor_sync(0xffffffffu, S1[r], off);
            S2[r] += __shfl_xor_sync(0xffffffffu, S2[r], off);
        }
    }
    const int wid = tid >> 5, lane = tid & 31;
    if (lane == 0) {
#pragma unroll
        for (int r = 0; r < 16; ++r) { red1[r][wid] = S1[r]; red2[r][wid] = S2[r]; }
    }
    __syncthreads();
    if (tid < 16) {
        float t1 = 0.f, t2 = 0.f;
#pragma unroll
        for (int w = 0; w < 8; ++w) { t1 += red1[tid][w]; t2 += red2[tid][w]; }
        const float src = s_src[tid];
        const float e1 = expf(src), e2 = expf(0.2f * src);
        const float inv = 1.0f / (e1 * t1 + e2 * t2);
        g_C[row0 + tid] = make_float2(e1 * inv, e2 * inv);
    }
}

// ---------------------------------------------------------------------------
// K4: fused masked-softmax x GEMM, cp.async double-buffered.
//     Per CTA: 32 output rows x 256 cols. grid=256 -> ~2 CTAs/SM.
// ---------------------------------------------------------------------------
struct K4Smem {
    __half sP [MT][72];          // P tile (fp16), padded
    __half sH [2][KC][264];      // h tiles, double-buffered, padded
    int    sAdj[2][MT][KC];      // adj chunks, double-buffered
    float2 sC  [MT];
    float  sSrc[MT];
};

__global__ void __launch_bounds__(256, 2) k4_main(const int* __restrict__ adj,
                                                  float* __restrict__ out) {
    extern __shared__ char smem_raw[];
    K4Smem& sm = *reinterpret_cast<K4Smem*>(smem_raw);

    const int tid  = threadIdx.x;
    const int row0 = blockIdx.x * MT;
    const int wid  = tid >> 5, lane = tid & 31;
    const int wm = (wid & 1) * 16;    // 2 warps over M (16 rows each)
    const int wn = (wid >> 1) * 64;   // 4 warps over N (64 cols each)

    if (tid < MT) {
        sm.sC[tid]   = g_C[row0 + tid];
        sm.sSrc[tid] = g_dE[row0 + tid].w;
    }

    // ---- prologue: prefetch chunk 0 ----
    {
        const int buf = 0, j0 = 0;
#pragma unroll
        for (int it = 0; it < 2; ++it) {            // adj: 512 x 16B
            const int idx = tid + it * 256;
            const int r = idx >> 4, c4 = (idx & 15) << 2;
            cp16(smem_u32(&sm.sAdj[buf][r][c4]),
                 &adj[(size_t)(row0 + r) * NROW + j0 + c4]);
        }
#pragma unroll
        for (int it = 0; it < 8; ++it) {            // h: 2048 x 16B
            const int idx = tid + it * 256;
            const int r = idx >> 5, c8 = (idx & 31) << 3;
            cp16(smem_u32(&sm.sH[buf][r][c8]),
                 &g_hh[(size_t)(j0 + r) * FDIM + c8]);
        }
        cp_commit();
    }

    float acc[8][4];
#pragma unroll
    for (int nt = 0; nt < 8; ++nt)
#pragma unroll
        for (int q = 0; q < 4; ++q) acc[nt][q] = 0.f;

    for (int s = 0; s < NROW / KC; ++s) {
        const int buf = s & 1;
        cp_wait0();
        __syncthreads();   // chunk s data visible; previous MMA done (sP/sAdj reusable)

        // ---- prefetch chunk s+1 into other buffer ----
        const int jn = (s + 1) * KC;
        if (jn < NROW) {
            const int nb = buf ^ 1;
#pragma unroll
            for (int it = 0; it < 2; ++it) {
                const int idx = tid + it * 256;
                const int r = idx >> 4, c4 = (idx & 15) << 2;
                cp16(smem_u32(&sm.sAdj[nb][r][c4]),
                     &adj[(size_t)(row0 + r) * NROW + jn + c4]);
            }
#pragma unroll
            for (int it = 0; it < 8; ++it) {
                const int idx = tid + it * 256;
                const int r = idx >> 5, c8 = (idx & 31) << 3;
                cp16(smem_u32(&sm.sH[nb][r][c8]),
                     &g_hh[(size_t)(jn + r) * FDIM + c8]);
            }
        }
        cp_commit();

        // ---- P-gen: 32x64 tile from smem adj ----
        const int j0 = s * KC;
#pragma unroll
        for (int it = 0; it < 2; ++it) {
            const int idx = tid + it * 256;
            const int m   = idx >> 4;
            const int jq  = (idx & 15) << 2;
            const int4 a4 = *(const int4*)(&sm.sAdj[buf][m][jq]);
            const float2 cc = sm.sC[m];
            const float src = sm.sSrc[m];
            const int av[4] = {a4.x, a4.y, a4.z, a4.w};
            float pv[4];
#pragma unroll
            for (int u = 0; u < 4; ++u) {
                const float4 de = __ldg(&g_dE[j0 + jq + u]);
                const float t = src + de.x;                        // src_i + dst_j
                const float p = (t > 0.f) ? (cc.x * de.y) : (cc.y * de.z);
                pv[u] = (av[u] > 0) ? p : 0.f;
            }
            *(__half2*)(&sm.sP[m][jq])     = __floats2half2_rn(pv[0], pv[1]);
            *(__half2*)(&sm.sP[m][jq + 2]) = __floats2half2_rn(pv[2], pv[3]);
        }
        __syncthreads();

        // ---- MMA: 4 k-steps of 16, warp covers 16(M) x 64(N) ----
#pragma unroll
        for (int kk = 0; kk < KC; kk += 16) {
            uint32_t Af[4];
            {
                const uint32_t addr = smem_u32(
                    &sm.sP[wm + (lane & 15)][kk + ((lane >> 4) << 3)]);
                asm volatile(
                    "ldmatrix.sync.aligned.m8n8.x4.shared.b16 "
                    "{%0,%1,%2,%3}, [%4];\n"
                    : "=r"(Af[0]), "=r"(Af[1]), "=r"(Af[2]), "=r"(Af[3])
                    : "r"(addr));
            }
#pragma unroll
            for (int nt2 = 0; nt2 < 4; ++nt2) {
                uint32_t Bf[4];
                const uint32_t baddr = smem_u32(
                    &sm.sH[buf][kk + (lane & 15)]
                          [wn + nt2 * 16 + ((lane >> 4) << 3)]);
                asm volatile(
                    "ldmatrix.sync.aligned.m8n8.x4.trans.shared.b16 "
                    "{%0,%1,%2,%3}, [%4];\n"
                    : "=r"(Bf[0]), "=r"(Bf[1]), "=r"(Bf[2]), "=r"(Bf[3])
                    : "r"(baddr));
                asm volatile(
                    "mma.sync.aligned.m16n8k16.row.col.f32.f16.f16.f32 "
                    "{%0,%1,%2,%3}, {%4,%5,%6,%7}, {%8,%9}, {%0,%1,%2,%3};\n"
                    : "+f"(acc[2 * nt2][0]), "+f"(acc[2 * nt2][1]),
                      "+f"(acc[2 * nt2][2]), "+f"(acc[2 * nt2][3])
                    : "r"(Af[0]), "r"(Af[1]), "r"(Af[2]), "r"(Af[3]),
                      "r"(Bf[0]), "r"(Bf[1]));
                asm volatile(
                    "mma.sync.aligned.m16n8k16.row.col.f32.f16.f16.f32 "
                    "{%0,%1,%2,%3}, {%4,%5,%6,%7}, {%8,%9}, {%0,%1,%2,%3};\n"
                    : "+f"(acc[2 * nt2 + 1][0]), "+f"(acc[2 * nt2 + 1][1]),
                      "+f"(acc[2 * nt2 + 1][2]), "+f"(acc[2 * nt2 + 1][3])
                    : "r"(Af[0]), "r"(Af[1]), "r"(Af[2]), "r"(Af[3]),
                      "r"(Bf[2]), "r"(Bf[3]));
            }
        }
    }

    // ---- epilogue: ReLU, fp32 store ----
    const int g  = lane >> 2;
    const int tq = lane & 3;
#pragma unroll
    for (int nt = 0; nt < 8; ++nt) {
        const int n  = wn + nt * 8 + tq * 2;
        const int r0 = row0 + wm + g;
        float2 v0 = make_float2(fmaxf(acc[nt][0], 0.f), fmaxf(acc[nt][1], 0.f));
        float2 v1 = make_float2(fmaxf(acc[nt][2], 0.f), fmaxf(acc[nt][3], 0.f));
        *(float2*)(&out[(size_t)r0 * FDIM + n])       = v0;
        *(float2*)(&out[(size_t)(r0 + 8) * FDIM + n]) = v1;
    }
}

// ---------------------------------------------------------------------------
extern "C" void kernel_launch(void* const* d_in, const int* in_sizes, int n_in,
                              void* d_out, int out_size) {
    const float* input_ = (const float*)d_in[0];
    const int*   adj    = (const int*)d_in[1];
    const float* W      = (const float*)d_in[2];
    const float* a      = (const float*)d_in[3];
    float*       out    = (float*)d_out;

    static int smem_set = 0;
    const int k4_smem = (int)sizeof(K4Smem);
    if (!smem_set) {
        cudaFuncSetAttribute(k4_main,
                             cudaFuncAttributeMaxDynamicSharedMemorySize,
                             k4_smem);
        smem_set = 1;
    }

    k1_gemm_h<<<NROW / 32, 256>>>(input_, W);
    k2_vec<<<NROW / 8, 256>>>(a);
    k3_stats<<<NROW / 16, 256>>>(adj);
    k4_main<<<NROW / MT, 256, k4_smem>>>(adj, out);
}